// round 5
// baseline (speedup 1.0000x reference)
#include <cuda_runtime.h>
#include <cuda_bf16.h>
#include <cuda_fp16.h>
#include <cstdint>

// ---------------------------------------------------------------------------
// CodebookLayer: out[m] = codebook[argmax_c (2*x.c - ||c||^2)]
//
// Round 5: FP8(e4m3) screening GEMM (mma.sync.m16n8k32, plain sm_100 legal),
// 4-stage cp.async pipeline, then exact fp64 rescore of candidates within
// MARGIN of each row's screened max.
// ---------------------------------------------------------------------------

#define MDIM 8192
#define CDIM 8192
#define KDIM 1024

__device__ __half   g_scores[(size_t)MDIM * CDIM];   // 128 MB scratch
__device__ uint8_t  g_x8 [(size_t)MDIM * KDIM];      // e4m3
__device__ uint8_t  g_cb8[(size_t)CDIM * KDIM];      // e4m3
__device__ float    g_c2[CDIM];

// ---------------- helpers ---------------------------------------------------
__device__ __forceinline__ uint32_t smem_u32(const void* p) {
    uint32_t a;
    asm("{ .reg .u64 t; cvta.to.shared.u64 t, %1; cvt.u32.u64 %0, t; }"
        : "=r"(a) : "l"(p));
    return a;
}
__device__ __forceinline__ void cp16(uint32_t s, const void* g) {
    asm volatile("cp.async.cg.shared.global [%0], [%1], 16;"
                 :: "r"(s), "l"(g) : "memory");
}
__device__ __forceinline__ void ldsm4(uint32_t* r, uint32_t addr) {
    asm volatile("ldmatrix.sync.aligned.m8n8.x4.shared.b16 {%0,%1,%2,%3}, [%4];"
        : "=r"(r[0]), "=r"(r[1]), "=r"(r[2]), "=r"(r[3]) : "r"(addr));
}
// m16n8k32 e4m3: same fragment register shape as bf16 m16n8k16
__device__ __forceinline__ void mma_fp8(float* d, const uint32_t* a,
                                        uint32_t b0, uint32_t b1) {
    asm volatile(
        "mma.sync.aligned.m16n8k32.row.col.f32.e4m3.e4m3.f32 "
        "{%0,%1,%2,%3}, {%4,%5,%6,%7}, {%8,%9}, {%0,%1,%2,%3};"
        : "+f"(d[0]), "+f"(d[1]), "+f"(d[2]), "+f"(d[3])
        : "r"(a[0]), "r"(a[1]), "r"(a[2]), "r"(a[3]), "r"(b0), "r"(b1));
}
__device__ __forceinline__ unsigned short fp8x2(float hi, float lo) {
    unsigned short r;
    asm("cvt.rn.satfinite.e4m3x2.f32 %0, %1, %2;" : "=h"(r) : "f"(hi), "f"(lo));
    return r;
}

// ---------------- kernel 0: fp32 -> e4m3 -------------------------------------
__global__ void convert_fp8(const float* __restrict__ s,
                            uint8_t* __restrict__ d, int n) {
    int i = (blockIdx.x * blockDim.x + threadIdx.x) * 8;
    if (i >= n) return;
    float4 v0 = *reinterpret_cast<const float4*>(s + i);
    float4 v1 = *reinterpret_cast<const float4*>(s + i + 4);
    uint2 o;
    o.x = (uint32_t)fp8x2(v0.y, v0.x) | ((uint32_t)fp8x2(v0.w, v0.z) << 16);
    o.y = (uint32_t)fp8x2(v1.y, v1.x) | ((uint32_t)fp8x2(v1.w, v1.z) << 16);
    *reinterpret_cast<uint2*>(d + i) = o;
}

// ---------------- kernel 1: codebook row norms (fp32 exact) ------------------
__global__ void c2_kernel(const float* __restrict__ cb, int C, int K) {
    int row  = blockIdx.x * (blockDim.x >> 5) + (threadIdx.x >> 5);
    int lane = threadIdx.x & 31;
    if (row >= C) return;
    const float4* p = reinterpret_cast<const float4*>(cb + (size_t)row * K);
    float s = 0.f;
    for (int i = lane; i < (K >> 2); i += 32) {
        float4 v = p[i];
        s += v.x * v.x + v.y * v.y + v.z * v.z + v.w * v.w;
    }
    #pragma unroll
    for (int m = 16; m; m >>= 1) s += __shfl_xor_sync(0xffffffffu, s, m);
    if (lane == 0) g_c2[row] = s;
}

// ---------------- kernel 2: fp8 screening GEMM -------------------------------
// BM=BN=128, BK=64 fp8, 256 thr (8 warps 2x4), warp tile 64x32, 4-stage cp.async
#define NSTAGE 4
#define STAGE_BYTES 16384          // A 8KB + B 8KB (128 rows x 64B each)

__device__ __forceinline__ void issue_stage(
    uint32_t sb, const uint8_t* Ag, const uint8_t* Bg,
    int s, int r0, int ch)
{
    int k0 = s * 64;
    uint32_t so = sb + (s & (NSTAGE - 1)) * STAGE_BYTES;
    uint32_t sw = (uint32_t)(ch ^ ((r0 >> 1) & 3)) << 4;
    int row = r0;
    cp16(so +        row * 64 + sw, Ag + (size_t)row * KDIM + k0 + ch * 16);
    cp16(so + 8192 + row * 64 + sw, Bg + (size_t)row * KDIM + k0 + ch * 16);
    row = r0 + 64;                                   // (64>>1)&3 == 0: same swizzle
    cp16(so +        row * 64 + sw, Ag + (size_t)row * KDIM + k0 + ch * 16);
    cp16(so + 8192 + row * 64 + sw, Bg + (size_t)row * KDIM + k0 + ch * 16);
}

__global__ __launch_bounds__(256, 2) void screen_gemm() {
    extern __shared__ __align__(128) char smem[];   // NSTAGE * 16KB = 64KB
    const uint32_t sb = smem_u32(smem);

    const int t    = threadIdx.x;
    const int lane = t & 31;
    const int wid  = t >> 5;
    const int wm   = wid >> 2;          // 0..1
    const int wn   = wid & 3;           // 0..3
    const int bm   = blockIdx.y * 128;
    const int bn   = blockIdx.x * 128;

    const int r0 = t >> 2;              // 0..63
    const int ch = t & 3;

    const uint8_t* Ag = g_x8  + (size_t)bm * KDIM;
    const uint8_t* Bg = g_cb8 + (size_t)bn * KDIM;

    const int NS = KDIM / 64;           // 16 k-stages

    #pragma unroll
    for (int s = 0; s < 3; s++) {
        issue_stage(sb, Ag, Bg, s, r0, ch);
        asm volatile("cp.async.commit_group;" ::: "memory");
    }

    float acc[4][4][4];
    #pragma unroll
    for (int i = 0; i < 4; i++)
        #pragma unroll
        for (int j = 0; j < 4; j++)
            #pragma unroll
            for (int k = 0; k < 4; k++) acc[i][j][k] = 0.f;

    for (int s = 0; s < NS; s++) {
        asm volatile("cp.async.wait_group 2;" ::: "memory");
        __syncthreads();

        const uint32_t As = sb + (s & (NSTAGE - 1)) * STAGE_BYTES;
        const uint32_t Bs = As + 8192;
        const int rbase = lane & 15;

        #pragma unroll
        for (int kk = 0; kk < 2; kk++) {             // two k32 groups per stage
            const int cin = kk * 2 + (lane >> 4);
            uint32_t a[4][4], b[2][4];
            #pragma unroll
            for (int mi = 0; mi < 4; mi++) {
                int row = wm * 64 + mi * 16 + rbase;
                ldsm4(a[mi], As + row * 64 +
                      ((uint32_t)(cin ^ ((row >> 1) & 3)) << 4));
            }
            #pragma unroll
            for (int g = 0; g < 2; g++) {
                int row = wn * 32 + g * 16 + rbase;
                ldsm4(b[g], Bs + row * 64 +
                      ((uint32_t)(cin ^ ((row >> 1) & 3)) << 4));
            }
            #pragma unroll
            for (int mi = 0; mi < 4; mi++)
                #pragma unroll
                for (int ni = 0; ni < 4; ni++)
                    mma_fp8(acc[mi][ni], a[mi],
                            b[ni >> 1][ni & 1], b[ni >> 1][(ni & 1) + 2]);
        }

        if (s + 3 < NS) issue_stage(sb, Ag, Bg, s + 3, r0, ch);
        asm volatile("cp.async.commit_group;" ::: "memory");   // empty group ok
    }

    // epilogue: screened score = 2*xc - c2 + 1024 (bias), stored fp16
    #pragma unroll
    for (int ni = 0; ni < 4; ni++) {
        int n0 = bn + wn * 32 + ni * 8 + 2 * (lane & 3);
        float c2a = 1024.f - g_c2[n0];
        float c2b = 1024.f - g_c2[n0 + 1];
        #pragma unroll
        for (int mi = 0; mi < 4; mi++) {
            int m0 = bm + wm * 64 + mi * 16 + (lane >> 2);
            __half2 h0 = __floats2half2_rn(2.f * acc[mi][ni][0] + c2a,
                                           2.f * acc[mi][ni][1] + c2b);
            *reinterpret_cast<__half2*>(&g_scores[(size_t)m0 * CDIM + n0]) = h0;
            __half2 h1 = __floats2half2_rn(2.f * acc[mi][ni][2] + c2a,
                                           2.f * acc[mi][ni][3] + c2b);
            *reinterpret_cast<__half2*>(&g_scores[(size_t)(m0 + 8) * CDIM + n0]) = h1;
        }
    }
}

// ---------------- kernel 3: select + exact fp64 rescore ----------------------
#define MARGIN 48.0f
#define MAXCAND 256

__global__ __launch_bounds__(256) void select_rescore(
    const float* __restrict__ x, const float* __restrict__ cb,
    float* __restrict__ out)
{
    __shared__ float  xs[KDIM];
    __shared__ float  smax[8];
    __shared__ double sred[2][8];
    __shared__ int    cand[MAXCAND];
    __shared__ int    ncand;

    const int m    = blockIdx.x;
    const int t    = threadIdx.x;
    const int lane = t & 31;
    const int wrp  = t >> 5;

    {
        const float4* src = reinterpret_cast<const float4*>(x + (size_t)m * KDIM);
        reinterpret_cast<float4*>(xs)[t] = src[t];
    }
    if (t == 0) ncand = 0;

    const uint4* row = reinterpret_cast<const uint4*>(g_scores + (size_t)m * CDIM);
    uint4 v[4];
    float lmax = -3.4e38f;
    #pragma unroll
    for (int j = 0; j < 4; j++) {
        v[j] = row[t + 256 * j];
        const __half2* h = reinterpret_cast<const __half2*>(&v[j]);
        #pragma unroll
        for (int e = 0; e < 4; e++) {
            float2 f = __half22float2(h[e]);
            lmax = fmaxf(lmax, fmaxf(f.x, f.y));
        }
    }
    #pragma unroll
    for (int o = 16; o; o >>= 1)
        lmax = fmaxf(lmax, __shfl_xor_sync(0xffffffffu, lmax, o));
    if (lane == 0) smax[wrp] = lmax;
    __syncthreads();
    float rowmax = smax[0];
    #pragma unroll
    for (int w = 1; w < 8; w++) rowmax = fmaxf(rowmax, smax[w]);
    const float thresh = rowmax - MARGIN;

    #pragma unroll
    for (int j = 0; j < 4; j++) {
        const __half2* h = reinterpret_cast<const __half2*>(&v[j]);
        #pragma unroll
        for (int e = 0; e < 4; e++) {
            float2 f = __half22float2(h[e]);
            int base = (t + 256 * j) * 8 + e * 2;
            if (f.x > thresh) { int p = atomicAdd(&ncand, 1); if (p < MAXCAND) cand[p] = base; }
            if (f.y > thresh) { int p = atomicAdd(&ncand, 1); if (p < MAXCAND) cand[p] = base + 1; }
        }
    }
    __syncthreads();
    int nc = min(ncand, MAXCAND);

    double bestS = -1e300;
    int    bestI = 0x7FFFFFFF;
    for (int ci = 0; ci < nc; ci++) {
        int c = cand[ci];
        const float* crow = cb + (size_t)c * KDIM;
        double s = 0.0, cc = 0.0;
        for (int d = t; d < KDIM; d += 256) {
            double cv = (double)crow[d];
            s  += (double)xs[d] * cv;
            cc += cv * cv;
        }
        #pragma unroll
        for (int o = 16; o; o >>= 1) {
            s  += __shfl_xor_sync(0xffffffffu, s,  o);
            cc += __shfl_xor_sync(0xffffffffu, cc, o);
        }
        if (lane == 0) { sred[0][wrp] = s; sred[1][wrp] = cc; }
        __syncthreads();
        double st = 0.0, ct = 0.0;
        #pragma unroll
        for (int w = 0; w < 8; w++) { st += sred[0][w]; ct += sred[1][w]; }
        __syncthreads();
        double sc = 2.0 * st - ct;
        if (sc > bestS || (sc == bestS && c < bestI)) { bestS = sc; bestI = c; }
    }

    const float4* src = reinterpret_cast<const float4*>(cb + (size_t)bestI * KDIM);
    float4* dst = reinterpret_cast<float4*>(out + (size_t)m * KDIM);
    dst[t] = src[t];
}

// ---------------- launch ------------------------------------------------------
extern "C" void kernel_launch(void* const* d_in, const int* in_sizes, int n_in,
                              void* d_out, int out_size)
{
    const float* x  = (const float*)d_in[0];   // [8192, 1024]
    const float* cb = (const float*)d_in[1];   // [8192, 1024]
    float* out = (float*)d_out;

    const int NX = MDIM * KDIM;
    const int NC = CDIM * KDIM;

    uint8_t *x8_p = nullptr, *cb8_p = nullptr;
    cudaGetSymbolAddress((void**)&x8_p, g_x8);
    cudaGetSymbolAddress((void**)&cb8_p, g_cb8);

    cudaFuncSetAttribute(screen_gemm,
                         cudaFuncAttributeMaxDynamicSharedMemorySize,
                         NSTAGE * STAGE_BYTES);

    convert_fp8<<<NX / 2048, 256>>>(x,  x8_p, NX);
    convert_fp8<<<NC / 2048, 256>>>(cb, cb8_p, NC);
    c2_kernel<<<CDIM / 8, 256>>>(cb, CDIM, KDIM);

    dim3 grid(CDIM / 128, MDIM / 128);
    screen_gemm<<<grid, 256, NSTAGE * STAGE_BYTES>>>();

    select_rescore<<<MDIM, 256>>>(x, cb, out);
}

// round 6
// speedup vs baseline: 1.0505x; 1.0505x over previous
#include <cuda_runtime.h>
#include <cuda_bf16.h>
#include <cuda_fp16.h>
#include <cstdint>

// ---------------------------------------------------------------------------
// CodebookLayer: out[m] = codebook[argmax_c (2*x.c - ||c||^2)]
//
// Round 6: bf16 screening GEMM (mma.sync m16n8k16), BK=64, 3-stage cp.async,
// fragment ping-pong + hoisted addressing; exact fp64 rescore (MARGIN 6).
// ---------------------------------------------------------------------------

#define MDIM 8192
#define CDIM 8192
#define KDIM 1024

__device__ __half        g_scores[(size_t)MDIM * CDIM];   // 128 MB scratch
__device__ __nv_bfloat16 g_xb [(size_t)MDIM * KDIM];
__device__ __nv_bfloat16 g_cbb[(size_t)CDIM * KDIM];
__device__ float         g_c2[CDIM];

// ---------------- helpers ---------------------------------------------------
__device__ __forceinline__ uint32_t smem_u32(const void* p) {
    uint32_t a;
    asm("{ .reg .u64 t; cvta.to.shared.u64 t, %1; cvt.u32.u64 %0, t; }"
        : "=r"(a) : "l"(p));
    return a;
}
__device__ __forceinline__ void cp16(uint32_t s, const void* g) {
    asm volatile("cp.async.cg.shared.global [%0], [%1], 16;"
                 :: "r"(s), "l"(g) : "memory");
}
__device__ __forceinline__ void ldsm4(uint32_t* r, uint32_t addr) {
    asm volatile("ldmatrix.sync.aligned.m8n8.x4.shared.b16 {%0,%1,%2,%3}, [%4];"
        : "=r"(r[0]), "=r"(r[1]), "=r"(r[2]), "=r"(r[3]) : "r"(addr));
}
__device__ __forceinline__ void mma_bf16(float* d, const uint32_t* a,
                                         uint32_t b0, uint32_t b1) {
    asm volatile(
        "mma.sync.aligned.m16n8k16.row.col.f32.bf16.bf16.f32 "
        "{%0,%1,%2,%3}, {%4,%5,%6,%7}, {%8,%9}, {%0,%1,%2,%3};"
        : "+f"(d[0]), "+f"(d[1]), "+f"(d[2]), "+f"(d[3])
        : "r"(a[0]), "r"(a[1]), "r"(a[2]), "r"(a[3]), "r"(b0), "r"(b1));
}

// ---------------- kernel 0: fp32 -> bf16 ------------------------------------
__global__ void convert_kernel(const float* __restrict__ s,
                               __nv_bfloat16* __restrict__ d, int n) {
    int i = (blockIdx.x * blockDim.x + threadIdx.x) * 4;
    if (i >= n) return;
    float4 v = *reinterpret_cast<const float4*>(s + i);
    __nv_bfloat162 p0 = {__float2bfloat16(v.x), __float2bfloat16(v.y)};
    __nv_bfloat162 p1 = {__float2bfloat16(v.z), __float2bfloat16(v.w)};
    *reinterpret_cast<__nv_bfloat162*>(d + i)     = p0;
    *reinterpret_cast<__nv_bfloat162*>(d + i + 2) = p1;
}

// ---------------- kernel 1: codebook row norms -------------------------------
__global__ void c2_kernel(const float* __restrict__ cb, int C, int K) {
    int row  = blockIdx.x * (blockDim.x >> 5) + (threadIdx.x >> 5);
    int lane = threadIdx.x & 31;
    if (row >= C) return;
    const float4* p = reinterpret_cast<const float4*>(cb + (size_t)row * K);
    float s = 0.f;
    for (int i = lane; i < (K >> 2); i += 32) {
        float4 v = p[i];
        s += v.x * v.x + v.y * v.y + v.z * v.z + v.w * v.w;
    }
    #pragma unroll
    for (int m = 16; m; m >>= 1) s += __shfl_xor_sync(0xffffffffu, s, m);
    if (lane == 0) g_c2[row] = s;
}

// ---------------- kernel 2: bf16 screening GEMM ------------------------------
// BM=BN=128, BK=64 (128B rows, SW128), 256 thr, 8 warps 2x4, warp tile 64x32,
// 3-stage cp.async, fragment ping-pong across k16 halves.
#define NSTAGE 3
#define TILE_BYTES  16384                   // 128 rows x 128 B
#define STAGE_BYTES (2 * TILE_BYTES)        // A + B
#define NS (KDIM / 64)                      // 16 k-stages

__global__ __launch_bounds__(256, 2) void screen_gemm() {
    extern __shared__ __align__(128) char smem[];   // 3 * 32 KB
    const uint32_t sb = smem_u32(smem);

    const int t    = threadIdx.x;
    const int lane = t & 31;
    const int wid  = t >> 5;
    const int wm   = wid >> 2;          // 0..1
    const int wn   = wid & 3;           // 0..3
    const int bm   = blockIdx.y * 128;
    const int bn   = blockIdx.x * 128;

    // ---- cp.async mapping: thread t -> row (t>>1), chunks 4*(t&1)+j ----
    const int crow = t >> 1;            // 0..127
    const int cch0 = (t & 1) * 4;       // 0 or 4
    uint32_t woff[4];
    #pragma unroll
    for (int j = 0; j < 4; j++)
        woff[j] = crow * 128 + (uint32_t)(((cch0 + j) ^ (crow & 7)) << 4);

    const __nv_bfloat16* pa = g_xb  + (size_t)(bm + crow) * KDIM + cch0 * 8;
    const __nv_bfloat16* pb = g_cbb + (size_t)(bn + crow) * KDIM + cch0 * 8;

    // ---- ldmatrix swizzle bases (per warp, per fragment row group) ----
    const int rb = lane & 15;
    uint32_t a_sw[4], b_sw[2];
    #pragma unroll
    for (int mi = 0; mi < 4; mi++) {
        int row = wm * 64 + mi * 16 + rb;
        a_sw[mi] = row * 128 + (uint32_t)((row & 7) << 4);
    }
    #pragma unroll
    for (int g = 0; g < 2; g++) {
        int row = wn * 32 + g * 16 + rb;
        b_sw[g] = row * 128 + (uint32_t)((row & 7) << 4) + TILE_BYTES;
    }
    const uint32_t lhalf = (uint32_t)(lane >> 4) << 4;   // chunk parity bit

    // ---- prologue: issue stages 0,1 ----
    #pragma unroll
    for (int s = 0; s < 2; s++) {
        uint32_t so = sb + s * STAGE_BYTES;
        #pragma unroll
        for (int j = 0; j < 4; j++) {
            cp16(so + woff[j],              pa + j * 8);
            cp16(so + TILE_BYTES + woff[j], pb + j * 8);
        }
        asm volatile("cp.async.commit_group;" ::: "memory");
        pa += 64; pb += 64;
    }

    float acc[4][4][4];
    #pragma unroll
    for (int i = 0; i < 4; i++)
        #pragma unroll
        for (int j = 0; j < 4; j++)
            #pragma unroll
            for (int k = 0; k < 4; k++) acc[i][j][k] = 0.f;

    uint32_t af[2][4][4], bf[2][2][4];
    int rbuf = 0, wbuf = 2;

    #define LOAD_HALF(pp, h)                                                  \
        {                                                                     \
            uint32_t cx = ((uint32_t)(2 * (h)) << 4) ^ lhalf;                 \
            ldsm4(af[pp][0], As + (a_sw[0] ^ cx));                            \
            ldsm4(af[pp][1], As + (a_sw[1] ^ cx));                            \
            ldsm4(af[pp][2], As + (a_sw[2] ^ cx));                            \
            ldsm4(af[pp][3], As + (b_sw[0] ^ cx) - TILE_BYTES + 0);           \
            ldsm4(bf[pp][0], As + (b_sw[0] ^ cx));                            \
            ldsm4(bf[pp][1], As + (b_sw[1] ^ cx));                            \
        }
    // NOTE: af[pp][3] line above must load A row group 3, fix: use a_sw[3].
    #undef LOAD_HALF
    #define LOAD_HALF(pp, h)                                                  \
        {                                                                     \
            uint32_t cx = ((uint32_t)(2 * (h)) << 4) ^ lhalf;                 \
            ldsm4(af[pp][0], As + (a_sw[0] ^ cx));                            \
            ldsm4(af[pp][1], As + (a_sw[1] ^ cx));                            \
            ldsm4(af[pp][2], As + (a_sw[2] ^ cx));                            \
            ldsm4(af[pp][3], As + (a_sw[3] ^ cx));                            \
            ldsm4(bf[pp][0], As + (b_sw[0] ^ cx));                            \
            ldsm4(bf[pp][1], As + (b_sw[1] ^ cx));                            \
        }

    #define MMA_HALF(pp)                                                      \
        {                                                                     \
            _Pragma("unroll")                                                 \
            for (int mi = 0; mi < 4; mi++)                                    \
                _Pragma("unroll")                                             \
                for (int ni = 0; ni < 4; ni++)                                \
                    mma_bf16(acc[mi][ni], af[pp][mi],                         \
                             bf[pp][ni >> 1][ni & 1],                         \
                             bf[pp][ni >> 1][(ni & 1) + 2]);                  \
        }

    for (int s = 0; s < NS; s++) {
        asm volatile("cp.async.wait_group 1;" ::: "memory");
        __syncthreads();

        // issue stage s+2 into wbuf (read in s-1, drained by the sync above)
        if (s + 2 < NS) {
            uint32_t so = sb + wbuf * STAGE_BYTES;
            #pragma unroll
            for (int j = 0; j < 4; j++) {
                cp16(so + woff[j],              pa + j * 8);
                cp16(so + TILE_BYTES + woff[j], pb + j * 8);
            }
            pa += 64; pb += 64;
        }
        asm volatile("cp.async.commit_group;" ::: "memory");
        wbuf = (wbuf == 2) ? 0 : wbuf + 1;

        const uint32_t As = sb + rbuf * STAGE_BYTES;
        rbuf = (rbuf == 2) ? 0 : rbuf + 1;

        // 4 k16 halves, ping-pong fragments
        LOAD_HALF(0, 0)
        #pragma unroll
        for (int h = 0; h < 4; h++) {
            if (h < 3) {
                if ((h & 1) == 0) { LOAD_HALF(1, h + 1) }
                else              { LOAD_HALF(0, h + 1) }
            }
            if ((h & 1) == 0) { MMA_HALF(0) } else { MMA_HALF(1) }
        }
    }

    // ---- epilogue: screened score = 2*xc - c2 + 1024, fp16 ----
    #pragma unroll
    for (int ni = 0; ni < 4; ni++) {
        int n0 = bn + wn * 32 + ni * 8 + 2 * (lane & 3);
        float c2a = 1024.f - g_c2[n0];
        float c2b = 1024.f - g_c2[n0 + 1];
        #pragma unroll
        for (int mi = 0; mi < 4; mi++) {
            int m0 = bm + wm * 64 + mi * 16 + (lane >> 2);
            __half2 h0 = __floats2half2_rn(2.f * acc[mi][ni][0] + c2a,
                                           2.f * acc[mi][ni][1] + c2b);
            *reinterpret_cast<__half2*>(&g_scores[(size_t)m0 * CDIM + n0]) = h0;
            __half2 h1 = __floats2half2_rn(2.f * acc[mi][ni][2] + c2a,
                                           2.f * acc[mi][ni][3] + c2b);
            *reinterpret_cast<__half2*>(&g_scores[(size_t)(m0 + 8) * CDIM + n0]) = h1;
        }
    }
}

// ---------------- kernel 3: select + exact fp64 rescore ----------------------
#define MARGIN 6.0f
#define MAXCAND 128

__global__ __launch_bounds__(256) void select_rescore(
    const float* __restrict__ x, const float* __restrict__ cb,
    float* __restrict__ out)
{
    __shared__ float  xs[KDIM];
    __shared__ float  smax[8];
    __shared__ double sred[2][8];
    __shared__ int    cand[MAXCAND];
    __shared__ int    ncand;

    const int m    = blockIdx.x;
    const int t    = threadIdx.x;
    const int lane = t & 31;
    const int wrp  = t >> 5;

    {
        const float4* src = reinterpret_cast<const float4*>(x + (size_t)m * KDIM);
        reinterpret_cast<float4*>(xs)[t] = src[t];
    }
    if (t == 0) ncand = 0;

    const uint4* row = reinterpret_cast<const uint4*>(g_scores + (size_t)m * CDIM);
    uint4 v[4];
    float lmax = -3.4e38f;
    #pragma unroll
    for (int j = 0; j < 4; j++) {
        v[j] = row[t + 256 * j];
        const __half2* h = reinterpret_cast<const __half2*>(&v[j]);
        #pragma unroll
        for (int e = 0; e < 4; e++) {
            float2 f = __half22float2(h[e]);
            lmax = fmaxf(lmax, fmaxf(f.x, f.y));
        }
    }
    #pragma unroll
    for (int o = 16; o; o >>= 1)
        lmax = fmaxf(lmax, __shfl_xor_sync(0xffffffffu, lmax, o));
    if (lane == 0) smax[wrp] = lmax;
    __syncthreads();
    float rowmax = smax[0];
    #pragma unroll
    for (int w = 1; w < 8; w++) rowmax = fmaxf(rowmax, smax[w]);
    const float thresh = rowmax - MARGIN;

    #pragma unroll
    for (int j = 0; j < 4; j++) {
        const __half2* h = reinterpret_cast<const __half2*>(&v[j]);
        #pragma unroll
        for (int e = 0; e < 4; e++) {
            float2 f = __half22float2(h[e]);
            int base = (t + 256 * j) * 8 + e * 2;
            if (f.x > thresh) { int p = atomicAdd(&ncand, 1); if (p < MAXCAND) cand[p] = base; }
            if (f.y > thresh) { int p = atomicAdd(&ncand, 1); if (p < MAXCAND) cand[p] = base + 1; }
        }
    }
    __syncthreads();
    int nc = min(ncand, MAXCAND);

    double bestS = -1e300;
    int    bestI = 0x7FFFFFFF;
    for (int ci = 0; ci < nc; ci++) {
        int c = cand[ci];
        const float* crow = cb + (size_t)c * KDIM;
        double s = 0.0, cc = 0.0;
        for (int d = t; d < KDIM; d += 256) {
            double cv = (double)crow[d];
            s  += (double)xs[d] * cv;
            cc += cv * cv;
        }
        #pragma unroll
        for (int o = 16; o; o >>= 1) {
            s  += __shfl_xor_sync(0xffffffffu, s,  o);
            cc += __shfl_xor_sync(0xffffffffu, cc, o);
        }
        if (lane == 0) { sred[0][wrp] = s; sred[1][wrp] = cc; }
        __syncthreads();
        double st = 0.0, ct = 0.0;
        #pragma unroll
        for (int w = 0; w < 8; w++) { st += sred[0][w]; ct += sred[1][w]; }
        __syncthreads();
        double sc = 2.0 * st - ct;
        if (sc > bestS || (sc == bestS && c < bestI)) { bestS = sc; bestI = c; }
    }

    const float4* src = reinterpret_cast<const float4*>(cb + (size_t)bestI * KDIM);
    float4* dst = reinterpret_cast<float4*>(out + (size_t)m * KDIM);
    dst[t] = src[t];
}

// ---------------- launch ------------------------------------------------------
extern "C" void kernel_launch(void* const* d_in, const int* in_sizes, int n_in,
                              void* d_out, int out_size)
{
    const float* x  = (const float*)d_in[0];   // [8192, 1024]
    const float* cb = (const float*)d_in[1];   // [8192, 1024]
    float* out = (float*)d_out;

    const int NX = MDIM * KDIM;
    const int NC = CDIM * KDIM;

    __nv_bfloat16 *xb_p = nullptr, *cb_p = nullptr;
    cudaGetSymbolAddress((void**)&xb_p, g_xb);
    cudaGetSymbolAddress((void**)&cb_p, g_cbb);

    cudaFuncSetAttribute(screen_gemm,
                         cudaFuncAttributeMaxDynamicSharedMemorySize,
                         NSTAGE * STAGE_BYTES);

    convert_kernel<<<NX / 1024, 256>>>(x,  xb_p, NX);
    convert_kernel<<<NC / 1024, 256>>>(cb, cb_p, NC);
    c2_kernel<<<CDIM / 8, 256>>>(cb, CDIM, KDIM);

    dim3 grid(CDIM / 128, MDIM / 128);
    screen_gemm<<<grid, 256, NSTAGE * STAGE_BYTES>>>();

    select_rescore<<<MDIM, 256>>>(x, cb, out);
}